// round 12
// baseline (speedup 1.0000x reference)
#include <cuda_runtime.h>
#include <cuda_bf16.h>

// CRF NLL, prob-domain. B=64, S=512, T=64 (START=62, END=63).
// R12 = R11 (fused fwd/bwd pair step, one packed shfl bundle per 2 steps)
//   + batch reduction folded into the forward kernel (threadfence-reduction
//     by the last-finishing CTA, fixed-order deterministic sum)
//   + renorm scale pre-multiplied into the staged k=0 emission (k==0 branch
//     removed from the hot loop).
//
// Inputs: d_in[0] feats f32 [B,S,T], d_in[1] transitions f32 [T,T],
//         d_in[2] mask i32 [B,S] (contiguous prefix), d_in[3] tags i32 [B,S]
// Output: f32 scalar sum_b (forward_b - gold_b)

#define B_    64
#define S_    512
#define T_    64
#define CHUNK 8

__device__ float g_res[B_];
__device__ int   g_cnt = 0;

static __device__ __forceinline__ __nv_bfloat162 u2b(unsigned u) {
    return *(__nv_bfloat162*)&u;
}
static __device__ __forceinline__ unsigned b2u(__nv_bfloat162 v) {
    return *(unsigned*)&v;
}
static __device__ __forceinline__ int max_exp(const unsigned* p) {
    const uint4* pv = (const uint4*)p;
    uint4 u0 = pv[0], u1 = pv[1], u2 = pv[2], u3 = pv[3];
    __nv_bfloat162 m0, m1, m2, m3;
    m0 = __hmax2(u2b(u0.x), u2b(u0.y));
    m0 = __hmax2(m0, __hmax2(u2b(u0.z), u2b(u0.w)));
    m1 = __hmax2(u2b(u1.x), u2b(u1.y));
    m1 = __hmax2(m1, __hmax2(u2b(u1.z), u2b(u1.w)));
    m2 = __hmax2(u2b(u2.x), u2b(u2.y));
    m2 = __hmax2(m2, __hmax2(u2b(u2.z), u2b(u2.w)));
    m3 = __hmax2(u2b(u3.x), u2b(u3.y));
    m3 = __hmax2(m3, __hmax2(u2b(u3.z), u2b(u3.w)));
    __nv_bfloat162 mm = __hmax2(__hmax2(m0, m1), __hmax2(m2, m3));
    __nv_bfloat16  mx = __hmax(__low2bfloat16(mm), __high2bfloat16(mm));
    unsigned short bits = *(unsigned short*)&mx;
    return (int)((bits >> 7) & 0xFF) - 127;
}
static __device__ __forceinline__ __nv_bfloat16 pow2_bf16(int e) {
    unsigned short sb = (unsigned short)((e + 127) << 7);
    return *(__nv_bfloat16*)&sb;
}
// single-chain 16-deep matvec + shfl combine (stitch / parity only)
static __device__ __forceinline__ __nv_bfloat16 matvec16(
    const unsigned* pp, const __nv_bfloat162* e2)
{
    const uint4* pv = (const uint4*)pp;
    uint4 u0 = pv[0], u1 = pv[1];
    __nv_bfloat162 a0 = __hmul2(u2b(u0.x), e2[0]);
    __nv_bfloat162 a1 = __hmul2(u2b(u0.y), e2[1]);
    __nv_bfloat162 a2 = __hmul2(u2b(u0.z), e2[2]);
    __nv_bfloat162 a3 = __hmul2(u2b(u0.w), e2[3]);
    a0 = __hfma2(u2b(u1.x), e2[4], a0);
    a1 = __hfma2(u2b(u1.y), e2[5], a1);
    a2 = __hfma2(u2b(u1.z), e2[6], a2);
    a3 = __hfma2(u2b(u1.w), e2[7], a3);
    __nv_bfloat162 s = __hadd2(__hadd2(a0, a1), __hadd2(a2, a3));
    unsigned t = __shfl_xor_sync(0xffffffffu, b2u(s), 8);
    s = __hadd2(s, u2b(t));
    t = __shfl_xor_sync(0xffffffffu, b2u(s), 16);
    s = __hadd2(s, u2b(t));
    return __hadd(__low2bfloat16(s), __high2bfloat16(s));
}

__global__ __launch_bounds__(256, 1) void crf_forward_kernel(
    const float* __restrict__ feats,
    const float* __restrict__ trans,
    const int*   __restrict__ mask,
    const int*   __restrict__ tags,
    float* __restrict__ out)
{
    __shared__ __align__(16) float    trans_sh[T_ * T_];
    __shared__ __align__(16) unsigned a_sh[2][T_ / 2];   // alpha bf16 pairs
    __shared__ __align__(16) unsigned w_sh[2][T_ / 2];   // w bf16 pairs
    __shared__ __align__(16) __nv_bfloat162 fab_sh[CHUNK][T_]; // (fa,fb)
    __shared__ int   tags_sh[S_];
    __shared__ float redg[8];
    __shared__ float redf[8];
    __shared__ int   redi[8];

    const int b    = blockIdx.x;
    const int tid  = threadIdx.x;
    const int lane = tid & 31;
    const int warp = tid >> 5;
    const int seg  = lane >> 3;                 // 0..3 : segment of 16
    const int j    = (warp << 3) | (lane & 7);  // 0..63 : output index
    const int r    = tid >> 6;                  // 0..3 : staging row group
    const int col  = tid & 63;                  // staging column

    const float* fbp   = feats + (size_t)b * S_ * T_;
    const int*   maskb = mask  + b * S_;
    const int*   tagsb = tags  + b * S_;

    // ---- stage transitions ----
    {
        const float4* t4 = (const float4*)trans;
        float4*       s4 = (float4*)trans_sh;
        #pragma unroll
        for (int i = 0; i < 4; ++i) s4[i * 256 + tid] = t4[i * 256 + tid];
    }
    // ---- tags + length ----
    int lenp = 0;
    #pragma unroll
    for (int k = 0; k < 2; ++k) {
        tags_sh[k * 256 + tid] = tagsb[k * 256 + tid];
        lenp += maskb[k * 256 + tid];
    }
    #pragma unroll
    for (int o = 16; o; o >>= 1) lenp += __shfl_xor_sync(0xffffffffu, lenp, o);
    if (lane == 0) redi[warp] = lenp;
    __syncthreads();
    int len = 0;
    #pragma unroll
    for (int w = 0; w < 8; ++w) len += redi[w];

    // ---- gold path score ----
    float g = 0.f;
    #pragma unroll
    for (int kk = 0; kk < 2; ++kk) {
        int s = kk * 256 + tid;
        if (s < len) {
            int tg = tags_sh[s];
            int pv = s ? tags_sh[s - 1] : (T_ - 2);
            g += fbp[s * T_ + tg] + trans_sh[pv * T_ + tg];
        }
    }
    if (tid == 0) g += trans_sh[tags_sh[len - 1] * T_ + (T_ - 1)];
    #pragma unroll
    for (int o = 16; o; o >>= 1) g += __shfl_xor_sync(0xffffffffu, g, o);
    if (lane == 0) redg[warp] = g;

    // ---- E slices: fwd column slice, bwd row slice ----
    __nv_bfloat162 ef2[8], eb2[8];
    #pragma unroll
    for (int m = 0; m < 8; ++m) {
        int i0 = seg * 16 + 2 * m;
        ef2[m] = __floats2bfloat162_rn(__expf(trans_sh[i0 * T_ + j]),
                                       __expf(trans_sh[(i0 + 1) * T_ + j]));
        eb2[m] = __floats2bfloat162_rn(__expf(trans_sh[j * T_ + i0]),
                                       __expf(trans_sh[j * T_ + i0 + 1]));
    }

    const int N = (len - 2) >> 1;        // paired steps
    const int p = (len - 2) & 1;         // parity: extra fwd step

    // ---- init alpha_0 and w_{len-1} ----
    if (tid < T_) {
        float a0 = __expf(fbp[tid] + trans_sh[(T_ - 2) * T_ + tid]);
        ((__nv_bfloat16*)a_sh[0])[tid] = __float2bfloat16(a0);
        float w0 = __expf(fbp[(len - 1) * T_ + tid] + trans_sh[tid * T_ + (T_ - 1)]);
        ((__nv_bfloat16*)w_sh[0])[tid] = __float2bfloat16(w0);
    }

    // ---- prefetch first chunk's emissions ----
    int n = 0;
    float frA0, frA1, frB0, frB1;
    {
        int ra0 = min(1 + r, S_ - 1), ra1 = min(5 + r, S_ - 1);
        frA0 = fbp[ra0 * T_ + col];
        frA1 = fbp[ra1 * T_ + col];
        int rb0 = max(len - 2 - r, 0), rb1 = max(len - 6 - r, 0);
        frB0 = fbp[rb0 * T_ + col];
        frB1 = fbp[rb1 * T_ + col];
    }
    __syncthreads();   // a_sh[0], w_sh[0], redg visible

    // ---- fused paired recurrence ----
    int cur = 0, ksumF = 0, ksumB = 0;

    while (n < N) {
        // renorm scale first (reads current p buffers, valid pre-barrier)
        __nv_bfloat162 scale2;
        {
            int keF = max_exp(a_sh[cur]);  ksumF += keF;
            int keB = max_exp(w_sh[cur]);  ksumB += keB;
            scale2 = __halves2bfloat162(pow2_bf16(-keF), pow2_bf16(-keB));
        }

        // stage interleaved (fa, fb); scale PRE-multiplied into row 0
        {
            __nv_bfloat162 f0 = __floats2bfloat162_rn(__expf(frA0), __expf(frB0));
            if (r == 0) f0 = __hmul2(f0, scale2);
            fab_sh[r][col]     = f0;
            fab_sh[r + 4][col] = __floats2bfloat162_rn(__expf(frA1), __expf(frB1));
        }

        // prefetch next chunk
        int nn = n + CHUNK;
        if (nn < N) {
            int ra0 = min(1 + nn + r, S_ - 1), ra1 = min(5 + nn + r, S_ - 1);
            frA0 = fbp[ra0 * T_ + col];
            frA1 = fbp[ra1 * T_ + col];
            int rb0 = max(len - 2 - nn - r, 0), rb1 = max(len - 6 - nn - r, 0);
            frB0 = fbp[rb0 * T_ + col];
            frB1 = fbp[rb1 * T_ + col];
        }

        const int cnt = min(CHUNK, N - n);
        __syncthreads();   // emissions visible; all prior reads done

        #pragma unroll
        for (int k = 0; k < CHUNK; ++k) {
            if (k >= cnt) break;   // block-uniform
            __nv_bfloat162 f2 = fab_sh[k][j];   // (fa, fb) one LDS.32
            const uint4* pa = (const uint4*)(a_sh[cur] + seg * 8);
            const uint4* pb = (const uint4*)(w_sh[cur] + seg * 8);
            uint4 ua0 = pa[0], ua1 = pa[1];
            uint4 ub0 = pb[0], ub1 = pb[1];
            __nv_bfloat162 aA0 = __hmul2(u2b(ua0.x), ef2[0]);
            __nv_bfloat162 aB0 = __hmul2(u2b(ub0.x), eb2[0]);
            __nv_bfloat162 aA1 = __hmul2(u2b(ua0.y), ef2[1]);
            __nv_bfloat162 aB1 = __hmul2(u2b(ub0.y), eb2[1]);
            __nv_bfloat162 aA2 = __hmul2(u2b(ua0.z), ef2[2]);
            __nv_bfloat162 aB2 = __hmul2(u2b(ub0.z), eb2[2]);
            __nv_bfloat162 aA3 = __hmul2(u2b(ua0.w), ef2[3]);
            __nv_bfloat162 aB3 = __hmul2(u2b(ub0.w), eb2[3]);
            aA0 = __hfma2(u2b(ua1.x), ef2[4], aA0);
            aB0 = __hfma2(u2b(ub1.x), eb2[4], aB0);
            aA1 = __hfma2(u2b(ua1.y), ef2[5], aA1);
            aB1 = __hfma2(u2b(ub1.y), eb2[5], aB1);
            aA2 = __hfma2(u2b(ua1.z), ef2[6], aA2);
            aB2 = __hfma2(u2b(ub1.z), eb2[6], aB2);
            aA3 = __hfma2(u2b(ua1.w), ef2[7], aA3);
            aB3 = __hfma2(u2b(ub1.w), eb2[7], aB3);
            __nv_bfloat162 sA = __hadd2(__hadd2(aA0, aA1), __hadd2(aA2, aA3));
            __nv_bfloat162 sB = __hadd2(__hadd2(aB0, aB1), __hadd2(aB2, aB3));
            __nv_bfloat16 hA = __hadd(__low2bfloat16(sA), __high2bfloat16(sA));
            __nv_bfloat16 hB = __hadd(__low2bfloat16(sB), __high2bfloat16(sB));
            __nv_bfloat162 h2 = __halves2bfloat162(hA, hB);
            unsigned t = __shfl_xor_sync(0xffffffffu, b2u(h2), 8);
            h2 = __hadd2(h2, u2b(t));
            t = __shfl_xor_sync(0xffffffffu, b2u(h2), 16);
            h2 = __hadd2(h2, u2b(t));
            __nv_bfloat162 q2 = __hmul2(h2, f2);
            if (seg == 0) {
                ((__nv_bfloat16*)a_sh[cur ^ 1])[j] = __low2bfloat16(q2);
                ((__nv_bfloat16*)w_sh[cur ^ 1])[j] = __high2bfloat16(q2);
            }
            __syncthreads();
            cur ^= 1;
        }
        n += CHUNK;
    }

    // ---- parity step: one extra forward step (emission row 1+N) ----
    int aidx = cur;
    if (p) {
        __nv_bfloat16 qa = matvec16(a_sh[cur] + seg * 8, ef2);
        qa = __hmul(qa, __float2bfloat16(__expf(fbp[(1 + N) * T_ + j])));
        if (seg == 0) ((__nv_bfloat16*)a_sh[cur ^ 1])[j] = qa;
        aidx = cur ^ 1;
        __syncthreads();
    }

    // ---- stitch: Z = sum_j (alpha_M E)_j * w_{M+1,j} ----
    {
        __nv_bfloat16 vh = matvec16(a_sh[aidx] + seg * 8, ef2);
        float vj = __bfloat162float(vh);
        float wj = __bfloat162float(((const __nv_bfloat16*)w_sh[cur])[j]);
        float z  = vj * wj;
        #pragma unroll
        for (int o = 16; o; o >>= 1) z += __shfl_xor_sync(0xffffffffu, z, o);
        if (lane == 0) redf[warp] = z;
    }
    __syncthreads();
    if (tid == 0) {
        float tot = 0.f;
        #pragma unroll
        for (int w = 0; w < 8; ++w) tot += redf[w];
        tot *= 0.25f;   // each j counted by 4 seg-threads
        float forward = (float)(ksumF + ksumB) * 0.69314718055994531f
                        + __logf(tot);
        float gold = 0.f;
        #pragma unroll
        for (int w = 0; w < 8; ++w) gold += redg[w];
        g_res[b] = forward - gold;

        // ---- fused deterministic reduction: last CTA sums in fixed order ----
        __threadfence();
        int done = atomicAdd(&g_cnt, 1);
        if (done == B_ - 1) {
            __threadfence();
            float acc = 0.f;
            #pragma unroll
            for (int i = 0; i < B_; ++i)
                acc += *((volatile float*)&g_res[i]);
            out[0] = acc;
            g_cnt = 0;   // reset for next graph replay
        }
    }
}

extern "C" void kernel_launch(void* const* d_in, const int* in_sizes, int n_in,
                              void* d_out, int out_size)
{
    const float* feats = (const float*)d_in[0];
    const float* trans = (const float*)d_in[1];
    const int*   mask  = (const int*)d_in[2];
    const int*   tags  = (const int*)d_in[3];
    float* out = (float*)d_out;

    crf_forward_kernel<<<B_, 256>>>(feats, trans, mask, tags, out);
}

// round 13
// speedup vs baseline: 1.2519x; 1.2519x over previous
#include <cuda_runtime.h>
#include <cuda_bf16.h>

// CRF NLL, prob-domain. B=64, S=512, T=64 (START=62, END=63).
// R13: each batch's forward and backward chains run in SEPARATE CTAs
//      (grid=128, one chain per CTA at R8's ~230cyc/step), stitched via
//      global memory by the second-arriving CTA of each pair; final batch
//      sum by the last stitcher (fixed order, deterministic).
//
// Inputs: d_in[0] feats f32 [B,S,T], d_in[1] transitions f32 [T,T],
//         d_in[2] mask i32 [B,S] (contiguous prefix), d_in[3] tags i32 [B,S]
// Output: f32 scalar sum_b (forward_b - gold_b)

#define B_    64
#define S_    512
#define T_    64
#define CHUNK 8

__device__ float g_vec[B_][2][T_];   // final chain vectors (fp32)
__device__ int   g_k[B_][2];         // renorm exponent sums
__device__ float g_gold[B_];
__device__ float g_res[B_];
__device__ int   g_pair[B_];         // per-batch arrival counters (init 0)
__device__ int   g_cnt = 0;          // stitch-completion counter

static __device__ __forceinline__ __nv_bfloat162 u2b(unsigned u) {
    return *(__nv_bfloat162*)&u;
}
static __device__ __forceinline__ unsigned b2u(__nv_bfloat162 v) {
    return *(unsigned*)&v;
}
static __device__ __forceinline__ int max_exp(const unsigned* p) {
    const uint4* pv = (const uint4*)p;
    uint4 u0 = pv[0], u1 = pv[1], u2 = pv[2], u3 = pv[3];
    __nv_bfloat162 m0, m1, m2, m3;
    m0 = __hmax2(u2b(u0.x), u2b(u0.y));
    m0 = __hmax2(m0, __hmax2(u2b(u0.z), u2b(u0.w)));
    m1 = __hmax2(u2b(u1.x), u2b(u1.y));
    m1 = __hmax2(m1, __hmax2(u2b(u1.z), u2b(u1.w)));
    m2 = __hmax2(u2b(u2.x), u2b(u2.y));
    m2 = __hmax2(m2, __hmax2(u2b(u2.z), u2b(u2.w)));
    m3 = __hmax2(u2b(u3.x), u2b(u3.y));
    m3 = __hmax2(m3, __hmax2(u2b(u3.z), u2b(u3.w)));
    __nv_bfloat162 mm = __hmax2(__hmax2(m0, m1), __hmax2(m2, m3));
    __nv_bfloat16  mx = __hmax(__low2bfloat16(mm), __high2bfloat16(mm));
    unsigned short bits = *(unsigned short*)&mx;
    return (int)((bits >> 7) & 0xFF) - 127;
}
static __device__ __forceinline__ __nv_bfloat16 pow2_bf16(int e) {
    unsigned short sb = (unsigned short)((e + 127) << 7);
    return *(__nv_bfloat16*)&sb;
}

__global__ __launch_bounds__(256, 1) void crf_forward_kernel(
    const float* __restrict__ feats,
    const float* __restrict__ trans,
    const int*   __restrict__ mask,
    const int*   __restrict__ tags,
    float* __restrict__ out)
{
    __shared__ __align__(16) float    trans_sh[T_ * T_];
    __shared__ __align__(16) unsigned p_sh[2][T_ / 2];    // bf16 pairs
    __shared__ __align__(16) __nv_bfloat16 f_sh[CHUNK][T_];
    __shared__ int   tags_sh[S_];
    __shared__ float redg[8];
    __shared__ float redf[8];
    __shared__ int   redi[8];
    __shared__ int   sh_old;

    const int bid  = blockIdx.x;
    const int b    = bid >> 1;
    const int side = bid & 1;                   // 0 = forward, 1 = backward
    const int tid  = threadIdx.x;
    const int lane = tid & 31;
    const int warp = tid >> 5;
    const int seg  = lane >> 3;                 // 0..3 : segment of 16
    const int j    = (warp << 3) | (lane & 7);  // 0..63 : state column
    const int r    = tid >> 6;                  // 0..3 : staging row group
    const int col  = tid & 63;                  // staging column

    const float* fbp   = feats + (size_t)b * S_ * T_;
    const int*   maskb = mask  + b * S_;
    const int*   tagsb = tags  + b * S_;

    // ---- stage transitions ----
    {
        const float4* t4 = (const float4*)trans;
        float4*       s4 = (float4*)trans_sh;
        #pragma unroll
        for (int i = 0; i < 4; ++i) s4[i * 256 + tid] = t4[i * 256 + tid];
    }
    // ---- length (both CTAs); tags only needed by fwd for gold ----
    int lenp = 0;
    #pragma unroll
    for (int k = 0; k < 2; ++k) {
        tags_sh[k * 256 + tid] = tagsb[k * 256 + tid];
        lenp += maskb[k * 256 + tid];
    }
    #pragma unroll
    for (int o = 16; o; o >>= 1) lenp += __shfl_xor_sync(0xffffffffu, lenp, o);
    if (lane == 0) redi[warp] = lenp;
    __syncthreads();
    int len = 0;
    #pragma unroll
    for (int w = 0; w < 8; ++w) len += redi[w];

    // ---- gold path score (fwd CTA only) ----
    if (side == 0) {
        float g = 0.f;
        #pragma unroll
        for (int kk = 0; kk < 2; ++kk) {
            int s = kk * 256 + tid;
            if (s < len) {
                int tg = tags_sh[s];
                int pv = s ? tags_sh[s - 1] : (T_ - 2);
                g += fbp[s * T_ + tg] + trans_sh[pv * T_ + tg];
            }
        }
        if (tid == 0) g += trans_sh[tags_sh[len - 1] * T_ + (T_ - 1)];
        #pragma unroll
        for (int o = 16; o; o >>= 1) g += __shfl_xor_sync(0xffffffffu, g, o);
        if (lane == 0) redg[warp] = g;
    }

    // ---- E slice for my chain direction ----
    __nv_bfloat162 e2[8];
    #pragma unroll
    for (int m = 0; m < 8; ++m) {
        int i0 = seg * 16 + 2 * m;
        if (side == 0)   // fwd: column slice E[i][j]
            e2[m] = __floats2bfloat162_rn(__expf(trans_sh[i0 * T_ + j]),
                                          __expf(trans_sh[(i0 + 1) * T_ + j]));
        else             // bwd: row slice E[j][i]
            e2[m] = __floats2bfloat162_rn(__expf(trans_sh[j * T_ + i0]),
                                          __expf(trans_sh[j * T_ + i0 + 1]));
    }

    const int total  = len - 2;
    const int bsteps = total >> 1;
    const int fsteps = total - bsteps;
    const int steps  = side ? bsteps : fsteps;
    const int base   = side ? (len - 2) : 1;
    const int dir    = side ? -1 : 1;

    // ---- init chain state ----
    if (tid < T_) {
        float v;
        if (side == 0)
            v = __expf(fbp[tid] + trans_sh[(T_ - 2) * T_ + tid]);
        else
            v = __expf(fbp[(len - 1) * T_ + tid] + trans_sh[tid * T_ + (T_ - 1)]);
        ((__nv_bfloat16*)p_sh[0])[tid] = __float2bfloat16(v);
    }

    // ---- prefetch first chunk's emissions ----
    int n = 0;
    float fr0, fr1;
    {
        int r0 = min(max(base + dir * r, 0), S_ - 1);
        int r1 = min(max(base + dir * (r + 4), 0), S_ - 1);
        fr0 = fbp[r0 * T_ + col];
        fr1 = fbp[r1 * T_ + col];
    }
    __syncthreads();   // p_sh[0], redg visible

    // ---- chain recurrence (R8/R11 ordering) ----
    int cur = 0, ksum = 0;

    while (n < steps) {
        // stage exp(f) for this chunk as bf16
        f_sh[r][col]     = __float2bfloat16(__expf(fr0));
        f_sh[r + 4][col] = __float2bfloat16(__expf(fr1));

        // prefetch next chunk
        int nn = n + CHUNK;
        if (nn < steps) {
            int r0 = min(max(base + dir * (nn + r), 0), S_ - 1);
            int r1 = min(max(base + dir * (nn + r + 4), 0), S_ - 1);
            fr0 = fbp[r0 * T_ + col];
            fr1 = fbp[r1 * T_ + col];
        }

        // exact power-of-2 renorm (redundant per-thread, off critical path)
        int ke = max_exp(p_sh[cur]);
        ksum += ke;
        __nv_bfloat16 scale = pow2_bf16(-ke);

        const int cnt = min(CHUNK, steps - n);
        __syncthreads();   // f_sh visible; all p reads done

        #pragma unroll
        for (int k = 0; k < CHUNK; ++k) {
            if (k >= cnt) break;   // block-uniform
            __nv_bfloat16 fk = f_sh[k][j];
            const uint4* pp = (const uint4*)(p_sh[cur] + seg * 8);
            uint4 u0 = pp[0], u1 = pp[1];
            __nv_bfloat162 a0 = __hmul2(u2b(u0.x), e2[0]);
            __nv_bfloat162 a1 = __hmul2(u2b(u0.y), e2[1]);
            __nv_bfloat162 a2 = __hmul2(u2b(u0.z), e2[2]);
            __nv_bfloat162 a3 = __hmul2(u2b(u0.w), e2[3]);
            a0 = __hfma2(u2b(u1.x), e2[4], a0);
            a1 = __hfma2(u2b(u1.y), e2[5], a1);
            a2 = __hfma2(u2b(u1.z), e2[6], a2);
            a3 = __hfma2(u2b(u1.w), e2[7], a3);
            __nv_bfloat162 s = __hadd2(__hadd2(a0, a1), __hadd2(a2, a3));
            unsigned t = __shfl_xor_sync(0xffffffffu, b2u(s), 8);
            s = __hadd2(s, u2b(t));
            t = __shfl_xor_sync(0xffffffffu, b2u(s), 16);
            s = __hadd2(s, u2b(t));
            __nv_bfloat16 h = __hadd(__low2bfloat16(s), __high2bfloat16(s));
            __nv_bfloat16 q = __hmul(h, fk);
            if (k == 0) q = __hmul(q, scale);
            if (seg == 0)
                ((__nv_bfloat16*)p_sh[cur ^ 1])[j] = q;
            __syncthreads();
            cur ^= 1;
        }
        n += CHUNK;
    }

    // ---- publish chain result ----
    if (tid < T_)
        g_vec[b][side][tid] =
            __bfloat162float(((const __nv_bfloat16*)p_sh[cur])[tid]);
    if (tid == 0) {
        g_k[b][side] = ksum;
        if (side == 0) {
            float gold = 0.f;
            #pragma unroll
            for (int w = 0; w < 8; ++w) gold += redg[w];
            g_gold[b] = gold;
        }
    }
    __threadfence();
    if (tid == 0) sh_old = atomicAdd(&g_pair[b], 1);
    __syncthreads();
    if (sh_old == 0) return;   // first arriver of the pair

    // ---- second arriver: stitch Z = (alpha_M E) . w_{M+1} ----
    __threadfence();
    const volatile float* aF = g_vec[b][0];
    const volatile float* wB = g_vec[b][1];
    float v = 0.f;
    #pragma unroll
    for (int m = 0; m < 16; ++m) {
        int i = seg * 16 + m;
        v = fmaf(aF[i], __expf(trans_sh[i * T_ + j]), v);
    }
    v += __shfl_xor_sync(0xffffffffu, v, 8);
    v += __shfl_xor_sync(0xffffffffu, v, 16);
    float z = v * wB[j];
    #pragma unroll
    for (int o = 16; o; o >>= 1) z += __shfl_xor_sync(0xffffffffu, z, o);
    if (lane == 0) redf[warp] = z;
    __syncthreads();
    if (tid == 0) {
        float tot = 0.f;
        #pragma unroll
        for (int w = 0; w < 8; ++w) tot += redf[w];
        tot *= 0.25f;   // each j counted by 4 seg-threads
        int ksA = *((volatile int*)&g_k[b][0]);
        int ksB = *((volatile int*)&g_k[b][1]);
        float forward = (float)(ksA + ksB) * 0.69314718055994531f + __logf(tot);
        float gold = *((volatile float*)&g_gold[b]);
        g_res[b] = forward - gold;
        g_pair[b] = 0;   // reset for next graph replay
        __threadfence();
        int done = atomicAdd(&g_cnt, 1);
        if (done == B_ - 1) {
            __threadfence();
            float acc = 0.f;
            #pragma unroll
            for (int i = 0; i < B_; ++i)
                acc += *((volatile float*)&g_res[i]);
            out[0] = acc;
            g_cnt = 0;
        }
    }
}

extern "C" void kernel_launch(void* const* d_in, const int* in_sizes, int n_in,
                              void* d_out, int out_size)
{
    const float* feats = (const float*)d_in[0];
    const float* trans = (const float*)d_in[1];
    const int*   mask  = (const int*)d_in[2];
    const int*   tags  = (const int*)d_in[3];
    float* out = (float*)d_out;

    crf_forward_kernel<<<2 * B_, 256>>>(feats, trans, mask, tags, out);
}

// round 14
// speedup vs baseline: 1.2616x; 1.0077x over previous
#include <cuda_runtime.h>
#include <cuda_bf16.h>

// CRF NLL, prob-domain. B=64, S=512, T=64 (START=62, END=63).
// R14: R13's chain-per-CTA split (grid=128: fwd/bwd CTA per batch) but each
//      CTA is 64 threads and each thread computes the FULL 64-deep bf16
//      contraction for its own state column (e2[32] register pairs).
//      -> zero shuffles in the hot loop, nw=2 barrier (~7cyc vs ~40).
//      Cross-CTA stitch + deterministic final sum as in R13.
//
// Inputs: d_in[0] feats f32 [B,S,T], d_in[1] transitions f32 [T,T],
//         d_in[2] mask i32 [B,S] (contiguous prefix), d_in[3] tags i32 [B,S]
// Output: f32 scalar sum_b (forward_b - gold_b)

#define B_    64
#define S_    512
#define T_    64
#define CHUNK 8

__device__ float g_vec[B_][2][T_];   // final chain vectors (fp32)
__device__ int   g_k[B_][2];         // renorm exponent sums
__device__ float g_gold[B_];
__device__ float g_res[B_];
__device__ int   g_pair[B_];         // per-batch arrival counters (init 0)
__device__ int   g_cnt = 0;          // stitch-completion counter

static __device__ __forceinline__ __nv_bfloat162 u2b(unsigned u) {
    return *(__nv_bfloat162*)&u;
}
static __device__ __forceinline__ __nv_bfloat16 pow2_bf16(int e) {
    unsigned short sb = (unsigned short)((e + 127) << 7);
    return *(__nv_bfloat16*)&sb;
}
// exponent (unbiased) of max over 64 bf16 values (8 uint4 broadcast loads)
static __device__ __forceinline__ int max_exp64(const unsigned* p) {
    const uint4* pv = (const uint4*)p;
    __nv_bfloat162 m0, m1, m2, m3;
    {
        uint4 u = pv[0];
        m0 = u2b(u.x); m1 = u2b(u.y); m2 = u2b(u.z); m3 = u2b(u.w);
    }
    #pragma unroll
    for (int i = 1; i < 8; ++i) {
        uint4 u = pv[i];
        m0 = __hmax2(m0, u2b(u.x));
        m1 = __hmax2(m1, u2b(u.y));
        m2 = __hmax2(m2, u2b(u.z));
        m3 = __hmax2(m3, u2b(u.w));
    }
    __nv_bfloat162 mm = __hmax2(__hmax2(m0, m1), __hmax2(m2, m3));
    __nv_bfloat16  mx = __hmax(__low2bfloat16(mm), __high2bfloat16(mm));
    unsigned short bits = *(unsigned short*)&mx;
    return (int)((bits >> 7) & 0xFF) - 127;
}

__global__ __launch_bounds__(64, 1) void crf_forward_kernel(
    const float* __restrict__ feats,
    const float* __restrict__ trans,
    const int*   __restrict__ mask,
    const int*   __restrict__ tags,
    float* __restrict__ out)
{
    __shared__ __align__(16) float    trans_sh[T_ * T_];
    __shared__ __align__(16) unsigned p_sh[2][T_ / 2];    // bf16 pairs
    __shared__ __align__(16) __nv_bfloat16 f_sh[CHUNK][T_];
    __shared__ float redg[2];
    __shared__ float redf[2];
    __shared__ int   redi[2];
    __shared__ int   sh_old;

    const int bid  = blockIdx.x;
    const int b    = bid >> 1;
    const int side = bid & 1;            // 0 = forward, 1 = backward
    const int tid  = threadIdx.x;        // == my state column j
    const int lane = tid & 31;
    const int warp = tid >> 5;

    const float* fbp   = feats + (size_t)b * S_ * T_;
    const int*   maskb = mask  + b * S_;
    const int*   tagsb = tags  + b * S_;

    // ---- stage transitions (1024 float4 / 64 thr = 16 each) ----
    {
        const float4* t4 = (const float4*)trans;
        float4*       s4 = (float4*)trans_sh;
        #pragma unroll
        for (int i = 0; i < 16; ++i) s4[i * 64 + tid] = t4[i * 64 + tid];
    }
    // ---- length ----
    int lenp = 0;
    #pragma unroll
    for (int k = 0; k < 8; ++k) lenp += maskb[k * 64 + tid];
    #pragma unroll
    for (int o = 16; o; o >>= 1) lenp += __shfl_xor_sync(0xffffffffu, lenp, o);
    if (lane == 0) redi[warp] = lenp;
    __syncthreads();   // trans_sh + redi visible
    const int len = redi[0] + redi[1];

    // ---- gold path score (fwd CTA only; one-time) ----
    if (side == 0) {
        float g = 0.f;
        #pragma unroll
        for (int kk = 0; kk < 8; ++kk) {
            int s = kk * 64 + tid;
            if (s < len) {
                int tg = tagsb[s];
                int pv = s ? tagsb[s - 1] : (T_ - 2);
                g += fbp[s * T_ + tg] + trans_sh[pv * T_ + tg];
            }
        }
        if (tid == 0) g += trans_sh[tagsb[len - 1] * T_ + (T_ - 1)];
        #pragma unroll
        for (int o = 16; o; o >>= 1) g += __shfl_xor_sync(0xffffffffu, g, o);
        if (lane == 0) redg[warp] = g;
    }

    // ---- full-depth E column/row as 32 bf16 pairs in registers ----
    unsigned e2[32];
    #pragma unroll
    for (int m = 0; m < 32; ++m) {
        float x, y;
        if (side == 0) {   // fwd: column E[i][j]
            x = __expf(trans_sh[(2 * m) * T_ + tid]);
            y = __expf(trans_sh[(2 * m + 1) * T_ + tid]);
        } else {           // bwd: row E[j][i]
            x = __expf(trans_sh[tid * T_ + 2 * m]);
            y = __expf(trans_sh[tid * T_ + 2 * m + 1]);
        }
        __nv_bfloat162 t = __floats2bfloat162_rn(x, y);
        e2[m] = *(unsigned*)&t;
    }

    const int total  = len - 2;
    const int bsteps = total >> 1;
    const int fsteps = total - bsteps;
    const int steps  = side ? bsteps : fsteps;
    const int base   = side ? (len - 2) : 1;
    const int dir    = side ? -1 : 1;

    // ---- init chain state ----
    {
        float v;
        if (side == 0)
            v = __expf(fbp[tid] + trans_sh[(T_ - 2) * T_ + tid]);
        else
            v = __expf(fbp[(len - 1) * T_ + tid] + trans_sh[tid * T_ + (T_ - 1)]);
        ((__nv_bfloat16*)p_sh[0])[tid] = __float2bfloat16(v);
    }

    // ---- prefetch first chunk's emissions (8 coalesced rows) ----
    int n = 0;
    float fr[CHUNK];
    #pragma unroll
    for (int k = 0; k < CHUNK; ++k) {
        int row = min(max(base + dir * k, 0), S_ - 1);
        fr[k] = fbp[row * T_ + tid];
    }
    __syncthreads();   // p_sh[0], redg visible

    // ---- chain recurrence: no shuffles, nw=2 barrier ----
    int cur = 0, ksum = 0;

    while (n < steps) {
        // stage exp(f) for this chunk as bf16 (off critical path)
        #pragma unroll
        for (int k = 0; k < CHUNK; ++k)
            f_sh[k][tid] = __float2bfloat16(__expf(fr[k]));

        // prefetch next chunk
        int nn = n + CHUNK;
        if (nn < steps) {
            #pragma unroll
            for (int k = 0; k < CHUNK; ++k) {
                int row = min(max(base + dir * (nn + k), 0), S_ - 1);
                fr[k] = fbp[row * T_ + tid];
            }
        }

        // exact power-of-2 renorm (redundant per-thread, off critical path)
        int ke = max_exp64(p_sh[cur]);
        ksum += ke;
        __nv_bfloat16 scale = pow2_bf16(-ke);

        const int cnt = min(CHUNK, steps - n);
        __syncthreads();   // f_sh visible; all p reads done

        #pragma unroll
        for (int k = 0; k < CHUNK; ++k) {
            if (k >= cnt) break;   // block-uniform
            __nv_bfloat16 fk = f_sh[k][tid];
            const uint4* pp = (const uint4*)p_sh[cur];
            __nv_bfloat162 a0, a1, a2, a3;
            {
                uint4 u = pp[0];
                a0 = __hmul2(u2b(u.x), u2b(e2[0]));
                a1 = __hmul2(u2b(u.y), u2b(e2[1]));
                a2 = __hmul2(u2b(u.z), u2b(e2[2]));
                a3 = __hmul2(u2b(u.w), u2b(e2[3]));
            }
            #pragma unroll
            for (int m = 1; m < 8; ++m) {
                uint4 u = pp[m];
                a0 = __hfma2(u2b(u.x), u2b(e2[4 * m + 0]), a0);
                a1 = __hfma2(u2b(u.y), u2b(e2[4 * m + 1]), a1);
                a2 = __hfma2(u2b(u.z), u2b(e2[4 * m + 2]), a2);
                a3 = __hfma2(u2b(u.w), u2b(e2[4 * m + 3]), a3);
            }
            __nv_bfloat162 s = __hadd2(__hadd2(a0, a1), __hadd2(a2, a3));
            __nv_bfloat16  h = __hadd(__low2bfloat16(s), __high2bfloat16(s));
            __nv_bfloat16  q = __hmul(h, fk);
            if (k == 0) q = __hmul(q, scale);
            ((__nv_bfloat16*)p_sh[cur ^ 1])[tid] = q;
            __syncthreads();
            cur ^= 1;
        }
        n += CHUNK;
    }

    // ---- publish chain result ----
    g_vec[b][side][tid] =
        __bfloat162float(((const __nv_bfloat16*)p_sh[cur])[tid]);
    if (tid == 0) {
        g_k[b][side] = ksum;
        if (side == 0) g_gold[b] = redg[0] + redg[1];
    }
    __threadfence();
    if (tid == 0) sh_old = atomicAdd(&g_pair[b], 1);
    __syncthreads();
    if (sh_old == 0) return;   // first arriver of the pair

    // ---- second arriver: stitch Z = (alpha_M E) . w_{M+1} (fp32, one-time) ----
    __threadfence();
    const volatile float* aF = g_vec[b][0];
    const volatile float* wB = g_vec[b][1];
    float v = 0.f;
    #pragma unroll
    for (int i = 0; i < T_; ++i)
        v = fmaf(aF[i], __expf(trans_sh[i * T_ + tid]), v);
    float z = v * wB[tid];
    #pragma unroll
    for (int o = 16; o; o >>= 1) z += __shfl_xor_sync(0xffffffffu, z, o);
    if (lane == 0) redf[warp] = z;
    __syncthreads();
    if (tid == 0) {
        float tot = redf[0] + redf[1];
        int ksA = *((volatile int*)&g_k[b][0]);
        int ksB = *((volatile int*)&g_k[b][1]);
        float forward = (float)(ksA + ksB) * 0.69314718055994531f + __logf(tot);
        float gold = *((volatile float*)&g_gold[b]);
        g_res[b] = forward - gold;
        g_pair[b] = 0;   // reset for next graph replay
        __threadfence();
        int done = atomicAdd(&g_cnt, 1);
        if (done == B_ - 1) {
            __threadfence();
            float acc = 0.f;
            #pragma unroll
            for (int i = 0; i < B_; ++i)
                acc += *((volatile float*)&g_res[i]);
            out[0] = acc;
            g_cnt = 0;
        }
    }
}

extern "C" void kernel_launch(void* const* d_in, const int* in_sizes, int n_in,
                              void* d_out, int out_size)
{
    const float* feats = (const float*)d_in[0];
    const float* trans = (const float*)d_in[1];
    const int*   mask  = (const int*)d_in[2];
    const int*   tags  = (const int*)d_in[3];
    float* out = (float*)d_out;

    crf_forward_kernel<<<2 * B_, 64>>>(feats, trans, mask, tags, out);
}

// round 15
// speedup vs baseline: 1.3324x; 1.0562x over previous
#include <cuda_runtime.h>
#include <cuda_bf16.h>

// CRF NLL, prob-domain. B=64, S=512, T=64 (START=62, END=63).
// R15 = R14 (chain-per-CTA, 64 thr, full-depth bf16 contraction per thread,
//            zero hot-loop shuffles) + software-pipelined chunk prologue:
//   - f_sh double-buffered; next chunk's exp/cvt/STS staging and the
//     chunk-after-next's LDG prefetch are spread 1-per-step into the k-loop
//   - per-chunk barrier removed (k-loop barriers give all ordering)
//   -> exactly 1 barrier per step; prologue = max_exp only.
//
// Inputs: d_in[0] feats f32 [B,S,T], d_in[1] transitions f32 [T,T],
//         d_in[2] mask i32 [B,S] (contiguous prefix), d_in[3] tags i32 [B,S]
// Output: f32 scalar sum_b (forward_b - gold_b)

#define B_    64
#define S_    512
#define T_    64
#define CHUNK 8

__device__ float g_vec[B_][2][T_];   // final chain vectors (fp32)
__device__ int   g_k[B_][2];         // renorm exponent sums
__device__ float g_gold[B_];
__device__ float g_res[B_];
__device__ int   g_pair[B_];         // per-batch arrival counters (init 0)
__device__ int   g_cnt = 0;          // stitch-completion counter

static __device__ __forceinline__ __nv_bfloat162 u2b(unsigned u) {
    return *(__nv_bfloat162*)&u;
}
static __device__ __forceinline__ __nv_bfloat16 pow2_bf16(int e) {
    unsigned short sb = (unsigned short)((e + 127) << 7);
    return *(__nv_bfloat16*)&sb;
}
// exponent (unbiased) of max over 64 bf16 values (8 uint4 broadcast loads)
static __device__ __forceinline__ int max_exp64(const unsigned* p) {
    const uint4* pv = (const uint4*)p;
    __nv_bfloat162 m0, m1, m2, m3;
    {
        uint4 u = pv[0];
        m0 = u2b(u.x); m1 = u2b(u.y); m2 = u2b(u.z); m3 = u2b(u.w);
    }
    #pragma unroll
    for (int i = 1; i < 8; ++i) {
        uint4 u = pv[i];
        m0 = __hmax2(m0, u2b(u.x));
        m1 = __hmax2(m1, u2b(u.y));
        m2 = __hmax2(m2, u2b(u.z));
        m3 = __hmax2(m3, u2b(u.w));
    }
    __nv_bfloat162 mm = __hmax2(__hmax2(m0, m1), __hmax2(m2, m3));
    __nv_bfloat16  mx = __hmax(__low2bfloat16(mm), __high2bfloat16(mm));
    unsigned short bits = *(unsigned short*)&mx;
    return (int)((bits >> 7) & 0xFF) - 127;
}

__global__ __launch_bounds__(64, 1) void crf_forward_kernel(
    const float* __restrict__ feats,
    const float* __restrict__ trans,
    const int*   __restrict__ mask,
    const int*   __restrict__ tags,
    float* __restrict__ out)
{
    __shared__ __align__(16) float    trans_sh[T_ * T_];
    __shared__ __align__(16) unsigned p_sh[2][T_ / 2];        // bf16 pairs
    __shared__ __align__(16) __nv_bfloat16 f_sh[2][CHUNK][T_]; // double-buffered
    __shared__ float redg[2];
    __shared__ float redf[2];
    __shared__ int   redi[2];
    __shared__ int   sh_old;

    const int bid  = blockIdx.x;
    const int b    = bid >> 1;
    const int side = bid & 1;            // 0 = forward, 1 = backward
    const int tid  = threadIdx.x;        // == my state column j
    const int lane = tid & 31;
    const int warp = tid >> 5;

    const float* fbp   = feats + (size_t)b * S_ * T_;
    const int*   maskb = mask  + b * S_;
    const int*   tagsb = tags  + b * S_;

    // ---- stage transitions (1024 float4 / 64 thr = 16 each) ----
    {
        const float4* t4 = (const float4*)trans;
        float4*       s4 = (float4*)trans_sh;
        #pragma unroll
        for (int i = 0; i < 16; ++i) s4[i * 64 + tid] = t4[i * 64 + tid];
    }
    // ---- length ----
    int lenp = 0;
    #pragma unroll
    for (int k = 0; k < 8; ++k) lenp += maskb[k * 64 + tid];
    #pragma unroll
    for (int o = 16; o; o >>= 1) lenp += __shfl_xor_sync(0xffffffffu, lenp, o);
    if (lane == 0) redi[warp] = lenp;
    __syncthreads();   // trans_sh + redi visible
    const int len = redi[0] + redi[1];

    // ---- gold path score (fwd CTA only; one-time) ----
    if (side == 0) {
        float g = 0.f;
        #pragma unroll
        for (int kk = 0; kk < 8; ++kk) {
            int s = kk * 64 + tid;
            if (s < len) {
                int tg = tagsb[s];
                int pv = s ? tagsb[s - 1] : (T_ - 2);
                g += fbp[s * T_ + tg] + trans_sh[pv * T_ + tg];
            }
        }
        if (tid == 0) g += trans_sh[tagsb[len - 1] * T_ + (T_ - 1)];
        #pragma unroll
        for (int o = 16; o; o >>= 1) g += __shfl_xor_sync(0xffffffffu, g, o);
        if (lane == 0) redg[warp] = g;
    }

    // ---- full-depth E column/row as 32 bf16 pairs in registers ----
    unsigned e2[32];
    #pragma unroll
    for (int m = 0; m < 32; ++m) {
        float x, y;
        if (side == 0) {   // fwd: column E[i][j]
            x = __expf(trans_sh[(2 * m) * T_ + tid]);
            y = __expf(trans_sh[(2 * m + 1) * T_ + tid]);
        } else {           // bwd: row E[j][i]
            x = __expf(trans_sh[tid * T_ + 2 * m]);
            y = __expf(trans_sh[tid * T_ + 2 * m + 1]);
        }
        __nv_bfloat162 t = __floats2bfloat162_rn(x, y);
        e2[m] = *(unsigned*)&t;
    }

    const int total  = len - 2;
    const int bsteps = total >> 1;
    const int fsteps = total - bsteps;
    const int steps  = side ? bsteps : fsteps;
    const int base   = side ? (len - 2) : 1;
    const int dir    = side ? -1 : 1;

    // clamped emission row for logical step index s (garbage rows never used)
    #define EMROW(s) (min(max(base + dir * (s), 0), S_ - 1))

    // ---- init chain state ----
    {
        float v;
        if (side == 0)
            v = __expf(fbp[tid] + trans_sh[(T_ - 2) * T_ + tid]);
        else
            v = __expf(fbp[(len - 1) * T_ + tid] + trans_sh[tid * T_ + (T_ - 1)]);
        ((__nv_bfloat16*)p_sh[0])[tid] = __float2bfloat16(v);
    }

    // ---- prologue: stage chunk 0 into f_sh[0]; prefetch chunk 1 into fr ----
    float fr[CHUNK];
    #pragma unroll
    for (int k = 0; k < CHUNK; ++k)
        f_sh[0][k][tid] = __float2bfloat16(__expf(fbp[EMROW(k) * T_ + tid]));
    #pragma unroll
    for (int k = 0; k < CHUNK; ++k)
        fr[k] = fbp[EMROW(CHUNK + k) * T_ + tid];
    __syncthreads();   // p_sh[0], f_sh[0], redg visible

    // ---- chain recurrence: 1 barrier/step, pipelined staging ----
    int n = 0, cur = 0, ksum = 0, fbuf = 0;

    while (n < steps) {
        // renorm from p_sh[cur] (ordering by previous step's barrier; next
        // overwrite of p_sh[cur] is at k=1, after k=0's barrier)
        int ke = max_exp64(p_sh[cur]);
        ksum += ke;
        __nv_bfloat16 scale = pow2_bf16(-ke);

        const int cnt = min(CHUNK, steps - n);

        #pragma unroll
        for (int k = 0; k < CHUNK; ++k) {
            if (k >= cnt) break;   // block-uniform
            __nv_bfloat16 fk = f_sh[fbuf][k][tid];
            const uint4* pp = (const uint4*)p_sh[cur];
            __nv_bfloat162 a0, a1, a2, a3;
            {
                uint4 u = pp[0];
                a0 = __hmul2(u2b(u.x), u2b(e2[0]));
                a1 = __hmul2(u2b(u.y), u2b(e2[1]));
                a2 = __hmul2(u2b(u.z), u2b(e2[2]));
                a3 = __hmul2(u2b(u.w), u2b(e2[3]));
            }
            #pragma unroll
            for (int m = 1; m < 8; ++m) {
                uint4 u = pp[m];
                a0 = __hfma2(u2b(u.x), u2b(e2[4 * m + 0]), a0);
                a1 = __hfma2(u2b(u.y), u2b(e2[4 * m + 1]), a1);
                a2 = __hfma2(u2b(u.z), u2b(e2[4 * m + 2]), a2);
                a3 = __hfma2(u2b(u.w), u2b(e2[4 * m + 3]), a3);
            }
            // shadow work (off critical path): stage row k of NEXT chunk
            // from fr[k], then refill fr[k] with chunk-after-next's row.
            f_sh[fbuf ^ 1][k][tid] = __float2bfloat16(__expf(fr[k]));
            fr[k] = fbp[EMROW(n + 2 * CHUNK + k) * T_ + tid];

            __nv_bfloat162 s = __hadd2(__hadd2(a0, a1), __hadd2(a2, a3));
            __nv_bfloat16  h = __hadd(__low2bfloat16(s), __high2bfloat16(s));
            __nv_bfloat16  q = __hmul(h, fk);
            if (k == 0) q = __hmul(q, scale);
            ((__nv_bfloat16*)p_sh[cur ^ 1])[tid] = q;
            __syncthreads();
            cur ^= 1;
        }
        fbuf ^= 1;
        n += CHUNK;
    }
    #undef EMROW

    // ---- publish chain result ----
    g_vec[b][side][tid] =
        __bfloat162float(((const __nv_bfloat16*)p_sh[cur])[tid]);
    if (tid == 0) {
        g_k[b][side] = ksum;
        if (side == 0) g_gold[b] = redg[0] + redg[1];
    }
    __threadfence();
    if (tid == 0) sh_old = atomicAdd(&g_pair[b], 1);
    __syncthreads();
    if (sh_old == 0) return;   // first arriver of the pair

    // ---- second arriver: stitch Z = (alpha_M E) . w_{M+1} (fp32, one-time) ----
    __threadfence();
    const volatile float* aF = g_vec[b][0];
    const volatile float* wB = g_vec[b][1];
    float v = 0.f;
    #pragma unroll
    for (int i = 0; i < T_; ++i)
        v = fmaf(aF[i], __expf(trans_sh[i * T_ + tid]), v);
    float z = v * wB[tid];
    #pragma unroll
    for (int o = 16; o; o >>= 1) z += __shfl_xor_sync(0xffffffffu, z, o);
    if (lane == 0) redf[warp] = z;
    __syncthreads();
    if (tid == 0) {
        float tot = redf[0] + redf[1];
        int ksA = *((volatile int*)&g_k[b][0]);
        int ksB = *((volatile int*)&g_k[b][1]);
        float forward = (float)(ksA + ksB) * 0.69314718055994531f + __logf(tot);
        float gold = *((volatile float*)&g_gold[b]);
        g_res[b] = forward - gold;
        g_pair[b] = 0;   // reset for next graph replay
        __threadfence();
        int done = atomicAdd(&g_cnt, 1);
        if (done == B_ - 1) {
            __threadfence();
            float acc = 0.f;
            #pragma unroll
            for (int i = 0; i < B_; ++i)
                acc += *((volatile float*)&g_res[i]);
            out[0] = acc;
            g_cnt = 0;
        }
    }
}

extern "C" void kernel_launch(void* const* d_in, const int* in_sizes, int n_in,
                              void* d_out, int out_size)
{
    const float* feats = (const float*)d_in[0];
    const float* trans = (const float*)d_in[1];
    const int*   mask  = (const int*)d_in[2];
    const int*   tags  = (const int*)d_in[3];
    float* out = (float*)d_out;

    crf_forward_kernel<<<2 * B_, 64>>>(feats, trans, mask, tags, out);
}